// round 10
// baseline (speedup 1.0000x reference)
#include <cuda_runtime.h>
#include <stdint.h>

// Emformer mask constants (compile-time, matching reference)
#define WCOLS  10303u              // (N-1) + RC*N + U = 63 + 2048 + 8192
#define NROWS  10304u              // RC*N + U + N
#define QROW0  2048u               // RC * N
#define SROW0  10240u              // QROW0 + U

// value at relative col j for a 2-threshold zone (x <= y):
//   j < x -> v0 ; x <= j < y -> v1 ; j >= y -> v2
__device__ __forceinline__ float selv(uint32_t j, uint32_t x, uint32_t y,
                                      float v0, float v1, float v2)
{
    return (j >= y) ? v2 : ((j >= x) ? v1 : v0);
}

__device__ __forceinline__ void st256_cs(float* p,
    float a0, float a1, float a2, float a3,
    float a4, float a5, float a6, float a7)
{
    asm volatile(
        "st.global.cs.v8.b32 [%0], {%1,%2,%3,%4,%5,%6,%7,%8};\n"
        :: "l"(p),
           "r"(__float_as_uint(a0)), "r"(__float_as_uint(a1)),
           "r"(__float_as_uint(a2)), "r"(__float_as_uint(a3)),
           "r"(__float_as_uint(a4)), "r"(__float_as_uint(a5)),
           "r"(__float_as_uint(a6)), "r"(__float_as_uint(a7))
        : "memory");
}

// Fill out[e0..e1) (global element indices), col = e - elem0.
// Main loop: 32B (8-elem) stores, 32B-aligned; scalar head/tail (<=7 each).
__device__ __forceinline__ void zone_fill(float* __restrict__ out,
    uint32_t elem0, uint32_t e0, uint32_t e1,
    uint32_t x, uint32_t y, float v0, float v1, float v2, uint32_t tid)
{
    const uint32_t aA = (e0 + 7u) & ~7u;     // first 32B-aligned elem
    const uint32_t aB = e1 & ~7u;            // last  32B-aligned end
    const uint32_t hEnd = (aA < e1) ? aA : e1;

    // head (<=7) + tail (<=7) scalars by low threads
    if (tid < 16u) {
        uint32_t e, lim;
        if (tid < 8u) { e = e0 + tid; lim = hEnd; }
        else {
            uint32_t tS = (aB > hEnd) ? aB : hEnd;
            e = tS + (tid - 8u); lim = e1;
        }
        if (e < lim)
            __stcs(out + e, selv(e - elem0, x, y, v0, v1, v2));
    }

    // j+7 >= x  <=>  j >= x-7 (clamped; clamp only forces the correct slow path)
    const uint32_t xm7 = (x > 7u) ? x - 7u : 0u;
    const uint32_t ym7 = (y > 7u) ? y - 7u : 0u;

    // unroll 4: batch independent 32B stores back-to-back per thread to deepen
    // the in-flight store queue (zone C has exactly 4 iterations per thread).
#pragma unroll 4
    for (uint32_t a = aA + 8u * tid; a < aB; a += 8u * 256u) {
        const uint32_t j = a - elem0;
        const bool px = j >= x,   py = j >= y;
        const bool qx = j >= xm7, qy = j >= ym7;   // endpoint j+7
        if ((px == qx) & (py == qy)) {             // no threshold inside span
            const float v = py ? v2 : (px ? v1 : v0);
            st256_cs(out + a, v, v, v, v, v, v, v, v);
        } else {                                   // rare: boundary span
            st256_cs(out + a,
                selv(j,      x, y, v0, v1, v2),
                selv(j + 1u, x, y, v0, v1, v2),
                selv(j + 2u, x, y, v0, v1, v2),
                selv(j + 3u, x, y, v0, v1, v2),
                selv(j + 4u, x, y, v0, v1, v2),
                selv(j + 5u, x, y, v0, v1, v2),
                selv(j + 6u, x, y, v0, v1, v2),
                selv(j + 7u, x, y, v0, v1, v2));
        }
    }
}

__global__ void __launch_bounds__(256)
emformer_mask_kernel(
    const int* __restrict__ indices,    // (63,) int32
    const int* __restrict__ last_idx,   // (1,)  int32
    const int* __restrict__ rc_tile,    // (63,9) bool as 4-byte
    const int* __restrict__ rc_last,    // (9,)
    const int* __restrict__ s_tile,     // (63,9)
    const int* __restrict__ s_last,     // (9,)
    float* __restrict__ out)            // (10304, 10303) float32
{
    const uint32_t r = blockIdx.x;      // one CTA per output row
    const uint32_t tid = threadIdx.x;

    int p;            // segment slot 0..63
    bool use_s;
    if (r < QROW0)      { p = (int)(r >> 5);           use_s = false; }
    else if (r < SROW0) { p = (int)((r - QROW0) >> 7); use_s = false; }
    else                { p = (int)(r - SROW0);        use_s = true;  }

    const int sid = (p < 63) ? indices[p] : last_idx[0];

    // Per-zone live thresholds: zone A [0,63), B [63,2111), C [2111,W)
    const uint32_t cA0 = (uint32_t)max(0, sid - 4);
    const uint32_t cA1 = (uint32_t)sid;
    const uint32_t cB0 = 63u + 32u * (uint32_t)sid;
    const uint32_t cB1 = cB0 + 32u;
    const uint32_t cC0 = 2111u + (uint32_t)max(0, 128 * sid - 64);
    const uint32_t cC1 = 2111u + (uint32_t)min(8192, 128 * (sid + 1));

    // 9-bit pattern: bit k = NOT mask[k] (output = logical_not of attend-mask)
    const int* m = use_s ? ((p < 63) ? s_tile + p * 9 : s_last)
                         : ((p < 63) ? rc_tile + p * 9 : rc_last);
    uint32_t pat = 0;
#pragma unroll
    for (int k = 0; k < 9; k++)
        pat |= (uint32_t)(m[k] == 0) << k;

    const float f0 = (float)((pat >> 0) & 1u), f1 = (float)((pat >> 1) & 1u),
                f2 = (float)((pat >> 2) & 1u), f3 = (float)((pat >> 3) & 1u),
                f4 = (float)((pat >> 4) & 1u), f5 = (float)((pat >> 5) & 1u),
                f6 = (float)((pat >> 6) & 1u), f7 = (float)((pat >> 7) & 1u),
                f8 = (float)((pat >> 8) & 1u);

    const uint32_t elem0 = r * WCOLS;   // < 1.07e8, fits uint32

    zone_fill(out, elem0, elem0,         elem0 + 63u,   cA0, cA1, f0, f1, f2, tid);
    zone_fill(out, elem0, elem0 + 63u,   elem0 + 2111u, cB0, cB1, f3, f4, f5, tid);
    zone_fill(out, elem0, elem0 + 2111u, elem0 + WCOLS, cC0, cC1, f6, f7, f8, tid);
}

extern "C" void kernel_launch(void* const* d_in, const int* in_sizes, int n_in,
                              void* d_out, int out_size)
{
    // metadata order: indices, utt_lengths(unused), rc_q_cols_mask_tile,
    //                 last_idx, last_utt_lengths(unused), last_rc_q_cols_mask,
    //                 s_cols_mask_tile, last_s_cols_mask
    const int* indices  = (const int*)d_in[0];
    const int* rc_tile  = (const int*)d_in[2];
    const int* last_idx = (const int*)d_in[3];
    const int* rc_last  = (const int*)d_in[5];
    const int* s_tile   = (const int*)d_in[6];
    const int* s_last   = (const int*)d_in[7];
    float*     out      = (float*)d_out;

    emformer_mask_kernel<<<NROWS, 256>>>(indices, last_idx, rc_tile, rc_last,
                                         s_tile, s_last, out);
}

// round 12
// speedup vs baseline: 1.0181x; 1.0181x over previous
#include <cuda_runtime.h>
#include <stdint.h>

// Emformer mask constants (compile-time, matching reference)
#define WCOLS  10303u              // (N-1) + RC*N + U = 63 + 2048 + 8192
#define NROWS  10304u              // RC*N + U + N
#define QROW0  2048u               // RC * N
#define SROW0  10240u              // QROW0 + U

// value at relative col j for a 2-threshold zone (x <= y):
//   j < x -> v0 ; x <= j < y -> v1 ; j >= y -> v2
__device__ __forceinline__ float selv(uint32_t j, uint32_t x, uint32_t y,
                                      float v0, float v1, float v2)
{
    return (j >= y) ? v2 : ((j >= x) ? v1 : v0);
}

__device__ __forceinline__ void st256_cs(float* p,
    float a0, float a1, float a2, float a3,
    float a4, float a5, float a6, float a7)
{
    asm volatile(
        "st.global.cs.v8.b32 [%0], {%1,%2,%3,%4,%5,%6,%7,%8};\n"
        :: "l"(p),
           "r"(__float_as_uint(a0)), "r"(__float_as_uint(a1)),
           "r"(__float_as_uint(a2)), "r"(__float_as_uint(a3)),
           "r"(__float_as_uint(a4)), "r"(__float_as_uint(a5)),
           "r"(__float_as_uint(a6)), "r"(__float_as_uint(a7))
        : "memory");
}

// Fill out[e0..e1) (global element indices), col = e - elem0.
// Main loop: 32B (8-elem) stores, 32B-aligned; scalar head/tail (<=7 each).
__device__ __forceinline__ void zone_fill(float* __restrict__ out,
    uint32_t elem0, uint32_t e0, uint32_t e1,
    uint32_t x, uint32_t y, float v0, float v1, float v2, uint32_t tid)
{
    const uint32_t aA = (e0 + 7u) & ~7u;     // first 32B-aligned elem
    const uint32_t aB = e1 & ~7u;            // last  32B-aligned end
    const uint32_t hEnd = (aA < e1) ? aA : e1;

    // head (<=7) + tail (<=7) scalars by low threads
    if (tid < 16u) {
        uint32_t e, lim;
        if (tid < 8u) { e = e0 + tid; lim = hEnd; }
        else {
            uint32_t tS = (aB > hEnd) ? aB : hEnd;
            e = tS + (tid - 8u); lim = e1;
        }
        if (e < lim)
            __stcs(out + e, selv(e - elem0, x, y, v0, v1, v2));
    }

    // j+7 >= x  <=>  j >= x-7 (clamped; clamp only forces the correct slow path)
    const uint32_t xm7 = (x > 7u) ? x - 7u : 0u;
    const uint32_t ym7 = (y > 7u) ? y - 7u : 0u;

    for (uint32_t a = aA + 8u * tid; a < aB; a += 8u * 256u) {
        const uint32_t j = a - elem0;
        const bool px = j >= x,   py = j >= y;
        const bool qx = j >= xm7, qy = j >= ym7;   // endpoint j+7
        if ((px == qx) & (py == qy)) {             // no threshold inside span
            const float v = py ? v2 : (px ? v1 : v0);
            st256_cs(out + a, v, v, v, v, v, v, v, v);
        } else {                                   // rare: boundary span
            st256_cs(out + a,
                selv(j,      x, y, v0, v1, v2),
                selv(j + 1u, x, y, v0, v1, v2),
                selv(j + 2u, x, y, v0, v1, v2),
                selv(j + 3u, x, y, v0, v1, v2),
                selv(j + 4u, x, y, v0, v1, v2),
                selv(j + 5u, x, y, v0, v1, v2),
                selv(j + 6u, x, y, v0, v1, v2),
                selv(j + 7u, x, y, v0, v1, v2));
        }
    }
}

__global__ void __launch_bounds__(256)
emformer_mask_kernel(
    const int* __restrict__ indices,    // (63,) int32
    const int* __restrict__ last_idx,   // (1,)  int32
    const int* __restrict__ rc_tile,    // (63,9) bool as 4-byte
    const int* __restrict__ rc_last,    // (9,)
    const int* __restrict__ s_tile,     // (63,9)
    const int* __restrict__ s_last,     // (9,)
    float* __restrict__ out)            // (10304, 10303) float32
{
    const uint32_t r = blockIdx.x;      // one CTA per output row
    const uint32_t tid = threadIdx.x;

    int p;            // segment slot 0..63
    bool use_s;
    if (r < QROW0)      { p = (int)(r >> 5);           use_s = false; }
    else if (r < SROW0) { p = (int)((r - QROW0) >> 7); use_s = false; }
    else                { p = (int)(r - SROW0);        use_s = true;  }

    const int sid = (p < 63) ? indices[p] : last_idx[0];

    // Per-zone live thresholds: zone A [0,63), B [63,2111), C [2111,W)
    const uint32_t cA0 = (uint32_t)max(0, sid - 4);
    const uint32_t cA1 = (uint32_t)sid;
    const uint32_t cB0 = 63u + 32u * (uint32_t)sid;
    const uint32_t cB1 = cB0 + 32u;
    const uint32_t cC0 = 2111u + (uint32_t)max(0, 128 * sid - 64);
    const uint32_t cC1 = 2111u + (uint32_t)min(8192, 128 * (sid + 1));

    // 9-bit pattern: bit k = NOT mask[k] (output = logical_not of attend-mask)
    const int* m = use_s ? ((p < 63) ? s_tile + p * 9 : s_last)
                         : ((p < 63) ? rc_tile + p * 9 : rc_last);
    uint32_t pat = 0;
#pragma unroll
    for (int k = 0; k < 9; k++)
        pat |= (uint32_t)(m[k] == 0) << k;

    const float f0 = (float)((pat >> 0) & 1u), f1 = (float)((pat >> 1) & 1u),
                f2 = (float)((pat >> 2) & 1u), f3 = (float)((pat >> 3) & 1u),
                f4 = (float)((pat >> 4) & 1u), f5 = (float)((pat >> 5) & 1u),
                f6 = (float)((pat >> 6) & 1u), f7 = (float)((pat >> 7) & 1u),
                f8 = (float)((pat >> 8) & 1u);

    const uint32_t elem0 = r * WCOLS;   // < 1.07e8, fits uint32

    zone_fill(out, elem0, elem0,         elem0 + 63u,   cA0, cA1, f0, f1, f2, tid);
    zone_fill(out, elem0, elem0 + 63u,   elem0 + 2111u, cB0, cB1, f3, f4, f5, tid);
    zone_fill(out, elem0, elem0 + 2111u, elem0 + WCOLS, cC0, cC1, f6, f7, f8, tid);
}

extern "C" void kernel_launch(void* const* d_in, const int* in_sizes, int n_in,
                              void* d_out, int out_size)
{
    // metadata order: indices, utt_lengths(unused), rc_q_cols_mask_tile,
    //                 last_idx, last_utt_lengths(unused), last_rc_q_cols_mask,
    //                 s_cols_mask_tile, last_s_cols_mask
    const int* indices  = (const int*)d_in[0];
    const int* rc_tile  = (const int*)d_in[2];
    const int* last_idx = (const int*)d_in[3];
    const int* rc_last  = (const int*)d_in[5];
    const int* s_tile   = (const int*)d_in[6];
    const int* s_last   = (const int*)d_in[7];
    float*     out      = (float*)d_out;

    emformer_mask_kernel<<<NROWS, 256>>>(indices, last_idx, rc_tile, rc_last,
                                         s_tile, s_last, out);
}

// round 13
// speedup vs baseline: 1.0207x; 1.0026x over previous
#include <cuda_runtime.h>
#include <stdint.h>

// Emformer mask constants (compile-time, matching reference)
#define WCOLS  10303u              // (N-1) + RC*N + U = 63 + 2048 + 8192
#define NROWS  10304u              // RC*N + U + N
#define QROW0  2048u               // RC * N
#define SROW0  10240u              // QROW0 + U

// value at relative col j for a 2-threshold zone (x <= y):
//   j < x -> v0 ; x <= j < y -> v1 ; j >= y -> v2
__device__ __forceinline__ float selv(uint32_t j, uint32_t x, uint32_t y,
                                      float v0, float v1, float v2)
{
    return (j >= y) ? v2 : ((j >= x) ? v1 : v0);
}

__device__ __forceinline__ void st256_cs(float* p,
    float a0, float a1, float a2, float a3,
    float a4, float a5, float a6, float a7)
{
    asm volatile(
        "st.global.cs.v8.b32 [%0], {%1,%2,%3,%4,%5,%6,%7,%8};\n"
        :: "l"(p),
           "r"(__float_as_uint(a0)), "r"(__float_as_uint(a1)),
           "r"(__float_as_uint(a2)), "r"(__float_as_uint(a3)),
           "r"(__float_as_uint(a4)), "r"(__float_as_uint(a5)),
           "r"(__float_as_uint(a6)), "r"(__float_as_uint(a7))
        : "memory");
}

// Fill out[e0..e1) (global element indices), col = e - elem0.
// Main loop: 32B (8-elem) stores, 32B-aligned; scalar head/tail (<=7 each).
__device__ __forceinline__ void zone_fill(float* __restrict__ out,
    uint32_t elem0, uint32_t e0, uint32_t e1,
    uint32_t x, uint32_t y, float v0, float v1, float v2, uint32_t tid)
{
    const uint32_t aA = (e0 + 7u) & ~7u;     // first 32B-aligned elem
    const uint32_t aB = e1 & ~7u;            // last  32B-aligned end
    const uint32_t hEnd = (aA < e1) ? aA : e1;

    // head (<=7) + tail (<=7) scalars by low threads
    if (tid < 16u) {
        uint32_t e, lim;
        if (tid < 8u) { e = e0 + tid; lim = hEnd; }
        else {
            uint32_t tS = (aB > hEnd) ? aB : hEnd;
            e = tS + (tid - 8u); lim = e1;
        }
        if (e < lim)
            __stcs(out + e, selv(e - elem0, x, y, v0, v1, v2));
    }

    // j+7 >= x  <=>  j >= x-7 (clamped; clamp only forces the correct slow path)
    const uint32_t xm7 = (x > 7u) ? x - 7u : 0u;
    const uint32_t ym7 = (y > 7u) ? y - 7u : 0u;

    for (uint32_t a = aA + 8u * tid; a < aB; a += 8u * 256u) {
        const uint32_t j = a - elem0;
        const bool px = j >= x,   py = j >= y;
        const bool qx = j >= xm7, qy = j >= ym7;   // endpoint j+7
        if ((px == qx) & (py == qy)) {             // no threshold inside span
            const float v = py ? v2 : (px ? v1 : v0);
            st256_cs(out + a, v, v, v, v, v, v, v, v);
        } else {                                   // rare: boundary span
            st256_cs(out + a,
                selv(j,      x, y, v0, v1, v2),
                selv(j + 1u, x, y, v0, v1, v2),
                selv(j + 2u, x, y, v0, v1, v2),
                selv(j + 3u, x, y, v0, v1, v2),
                selv(j + 4u, x, y, v0, v1, v2),
                selv(j + 5u, x, y, v0, v1, v2),
                selv(j + 6u, x, y, v0, v1, v2),
                selv(j + 7u, x, y, v0, v1, v2));
        }
    }
}

__global__ void __launch_bounds__(256)
emformer_mask_kernel(
    const int* __restrict__ indices,    // (63,) int32
    const int* __restrict__ last_idx,   // (1,)  int32
    const int* __restrict__ rc_tile,    // (63,9) bool as 4-byte
    const int* __restrict__ rc_last,    // (9,)
    const int* __restrict__ s_tile,     // (63,9)
    const int* __restrict__ s_last,     // (9,)
    float* __restrict__ out)            // (10304, 10303) float32
{
    const uint32_t r = blockIdx.x;      // one CTA per output row
    const uint32_t tid = threadIdx.x;

    int p;            // segment slot 0..63
    bool use_s;
    if (r < QROW0)      { p = (int)(r >> 5);           use_s = false; }
    else if (r < SROW0) { p = (int)((r - QROW0) >> 7); use_s = false; }
    else                { p = (int)(r - SROW0);        use_s = true;  }

    const int sid = (p < 63) ? indices[p] : last_idx[0];

    // Per-zone live thresholds: zone A [0,63), B [63,2111), C [2111,W)
    const uint32_t cA0 = (uint32_t)max(0, sid - 4);
    const uint32_t cA1 = (uint32_t)sid;
    const uint32_t cB0 = 63u + 32u * (uint32_t)sid;
    const uint32_t cB1 = cB0 + 32u;
    const uint32_t cC0 = 2111u + (uint32_t)max(0, 128 * sid - 64);
    const uint32_t cC1 = 2111u + (uint32_t)min(8192, 128 * (sid + 1));

    // 9-bit pattern: bit k = NOT mask[k] (output = logical_not of attend-mask)
    const int* m = use_s ? ((p < 63) ? s_tile + p * 9 : s_last)
                         : ((p < 63) ? rc_tile + p * 9 : rc_last);
    uint32_t pat = 0;
#pragma unroll
    for (int k = 0; k < 9; k++)
        pat |= (uint32_t)(m[k] == 0) << k;

    const float f0 = (float)((pat >> 0) & 1u), f1 = (float)((pat >> 1) & 1u),
                f2 = (float)((pat >> 2) & 1u), f3 = (float)((pat >> 3) & 1u),
                f4 = (float)((pat >> 4) & 1u), f5 = (float)((pat >> 5) & 1u),
                f6 = (float)((pat >> 6) & 1u), f7 = (float)((pat >> 7) & 1u),
                f8 = (float)((pat >> 8) & 1u);

    const uint32_t elem0 = r * WCOLS;   // < 1.07e8, fits uint32

    zone_fill(out, elem0, elem0,         elem0 + 63u,   cA0, cA1, f0, f1, f2, tid);
    zone_fill(out, elem0, elem0 + 63u,   elem0 + 2111u, cB0, cB1, f3, f4, f5, tid);
    zone_fill(out, elem0, elem0 + 2111u, elem0 + WCOLS, cC0, cC1, f6, f7, f8, tid);
}

extern "C" void kernel_launch(void* const* d_in, const int* in_sizes, int n_in,
                              void* d_out, int out_size)
{
    // metadata order: indices, utt_lengths(unused), rc_q_cols_mask_tile,
    //                 last_idx, last_utt_lengths(unused), last_rc_q_cols_mask,
    //                 s_cols_mask_tile, last_s_cols_mask
    const int* indices  = (const int*)d_in[0];
    const int* rc_tile  = (const int*)d_in[2];
    const int* last_idx = (const int*)d_in[3];
    const int* rc_last  = (const int*)d_in[5];
    const int* s_tile   = (const int*)d_in[6];
    const int* s_last   = (const int*)d_in[7];
    float*     out      = (float*)d_out;

    emformer_mask_kernel<<<NROWS, 256>>>(indices, last_idx, rc_tile, rc_last,
                                         s_tile, s_last, out);
}